// round 6
// baseline (speedup 1.0000x reference)
#include <cuda_runtime.h>

// LSTM seq2seq: B=64, T=512, F=64, H=512, FUT=96 — persistent-kernel design.
//  - 2 persistent kernels (encoder pipelined L0+L1; decoder) with software grid
//    barriers; weights resident in shared memory; c-state in registers.
//  - Gate-interleaved packed weights, fma.rn.f32x2 inner product.
//  - Decoder FC feedback folded into cell0 weights; final FC batched.

#define BB 64
#define TT 512
#define FF 64
#define HH 512
#define FUT 96
#define BH (BB*HH)          // 32768

#define NBLK 128
#define NTHR 256
#define WSS   514           // padded k-stride (ulonglong2) for K=512 tiles
#define WSS64 66            // padded k-stride for K=64 tiles
#define HS_PAD 36           // padded floats per staged activation row

// ---------------- device scratch ----------------
__device__ float  g_y0[TT*BB*HH];         // enc L0 h history (64MB)
__device__ float  g_h1hist[FUT*BB*HH];    // decoder L1 h history
__device__ float  g_zero[BH];
__device__ float  g_c0[BH], g_c1[BH];
__device__ float  g_h1A[BH], g_h1B[BH], g_h0A[BH], g_h0B[BH];

__device__ float4 g_pW_enc_ih0[HH*FF];
__device__ float4 g_pW_enc_hh0[HH*HH];
__device__ float4 g_pW_enc_ih1[HH*HH];
__device__ float4 g_pW_enc_hh1[HH*HH];
__device__ float4 g_pW_dec_ih0[HH*FF];
__device__ float4 g_pW_dec_hh0[HH*HH];
__device__ float4 g_pW_dec_ih1[HH*HH];
__device__ float4 g_pW_dec_hh1[HH*HH];
__device__ float4 g_pW_dec0c[HH*HH];      // combined Wih0 @ fcW
__device__ float4 g_pb_enc0[HH], g_pb_enc1[HH], g_pb_dec0[HH], g_pb_dec1[HH], g_pb_dec0c[HH];

__device__ unsigned g_bcount;
__device__ unsigned g_bgen;

// ---------------- f32x2 helpers ----------------
__device__ __forceinline__ unsigned long long bcast2(float v) {
    unsigned int u = __float_as_uint(v);
    unsigned long long r;
    asm("mov.b64 %0, {%1, %1};" : "=l"(r) : "r"(u));
    return r;
}
__device__ __forceinline__ unsigned long long pack2(float a, float b) {
    unsigned long long r;
    asm("mov.b64 %0, {%1, %2};" : "=l"(r) : "r"(__float_as_uint(a)), "r"(__float_as_uint(b)));
    return r;
}
__device__ __forceinline__ float2 unpack2(unsigned long long v) {
    unsigned int lo, hi;
    asm("mov.b64 {%0, %1}, %2;" : "=r"(lo), "=r"(hi) : "l"(v));
    return make_float2(__uint_as_float(lo), __uint_as_float(hi));
}
__device__ __forceinline__ void ffma2(unsigned long long& d, unsigned long long a, unsigned long long b) {
    asm("fma.rn.f32x2 %0, %1, %2, %0;" : "+l"(d) : "l"(a), "l"(b));
}

// ---------------- grid barrier (sense-free monotone generation) ----------------
__device__ __forceinline__ void grid_barrier(unsigned target) {
    __syncthreads();
    if (threadIdx.x == 0) {
        __threadfence();
        if (atomicAdd(&g_bcount, 1) == NBLK - 1) {
            atomicExch(&g_bcount, 0);
            __threadfence();
            atomicAdd(&g_bgen, 1);
        } else {
            while (atomicAdd(&g_bgen, 0) < target) { }
        }
        __threadfence();
    }
    __syncthreads();
}

// ---------------- inner dot over a 32-k chunk ----------------
__device__ __forceinline__ void dot32(ulonglong2& acc, const ulonglong2* __restrict__ w,
                                      const float* __restrict__ hrow) {
#pragma unroll
    for (int kk = 0; kk < 32; kk += 4) {
        float4 hv = *(const float4*)(hrow + kk);
        ulonglong2 w0 = w[kk + 0], w1 = w[kk + 1], w2 = w[kk + 2], w3 = w[kk + 3];
        unsigned long long h0 = bcast2(hv.x), h1 = bcast2(hv.y),
                           h2 = bcast2(hv.z), h3 = bcast2(hv.w);
        ffma2(acc.x, h0, w0.x); ffma2(acc.y, h0, w0.y);
        ffma2(acc.x, h1, w1.x); ffma2(acc.y, h1, w1.y);
        ffma2(acc.x, h2, w2.x); ffma2(acc.y, h2, w2.y);
        ffma2(acc.x, h3, w3.x); ffma2(acc.y, h3, w3.y);
    }
}

// K=512 phase with register prefetch. Activations x: [64][512] row-major in global.
// Accumulates into acc0 (weights Wa) and/or acc1 (weights Wb), both smem tiles.
template <bool A0, bool A1>
__device__ __forceinline__ void phase512(
    ulonglong2& acc0, ulonglong2& acc1,
    const float* __restrict__ x,
    const ulonglong2* __restrict__ Wa, const ulonglong2* __restrict__ Wb,
    float* hs, int tid, int jl, int r)
{
    int rr0 = tid >> 5;
    int kk0 = tid & 31;
    float pf[8];
#pragma unroll
    for (int u = 0; u < 8; u++) pf[u] = x[(rr0 + u * 8) * HH + kk0];

    for (int kc = 0; kc < HH; kc += 32) {
        __syncthreads();                     // prior chunk fully consumed
#pragma unroll
        for (int u = 0; u < 8; u++) hs[(rr0 + u * 8) * HS_PAD + kk0] = pf[u];
        __syncthreads();                     // chunk visible
        if (kc + 32 < HH) {
#pragma unroll
            for (int u = 0; u < 8; u++) pf[u] = x[(rr0 + u * 8) * HH + kc + 32 + kk0];
        }
        const float* hrow = hs + r * HS_PAD;
        if (A0) dot32(acc0, Wa + jl * WSS + kc, hrow);
        if (A1) dot32(acc1, Wb + jl * WSS + kc, hrow);
    }
    __syncthreads();
}

// K=64 phase (input_seq projection), xstride in floats.
__device__ __forceinline__ void phase64(
    ulonglong2& acc, const float* __restrict__ x, long xstride,
    const ulonglong2* __restrict__ W, float* hs, int tid, int jl, int r)
{
    int rr0 = tid >> 5;
    int kk0 = tid & 31;
    for (int kc = 0; kc < FF; kc += 32) {
        __syncthreads();
#pragma unroll
        for (int u = 0; u < 8; u++)
            hs[(rr0 + u * 8) * HS_PAD + kk0] = x[(long)(rr0 + u * 8) * xstride + kc + kk0];
        __syncthreads();
        dot32(acc, W + jl * WSS64 + kc, hs + r * HS_PAD);
    }
    __syncthreads();
}

__device__ __forceinline__ float cellfin(ulonglong2 acc, float& c) {
    float2 vif = unpack2(acc.x);
    float2 vgo = unpack2(acc.y);
    float si = 1.f / (1.f + __expf(-vif.x));
    float sf = 1.f / (1.f + __expf(-vif.y));
    float so = 1.f / (1.f + __expf(-vgo.y));
    float cn = sf * c + si * tanhf(vgo.x);
    c = cn;
    return so * tanhf(cn);
}

// ---------------- persistent encoder: L0 + L1 software-pipelined ----------------
// slot s: L0 computes y0[s] (inputs x[s], y0[s-1]); L1 computes h1[s-1]
// (inputs y0[s-1], h1[s-2]). One grid barrier per slot; 513 slots.
#define ENC_SMEM (((3*4*WSS + 4*WSS64) * 16) + 64*HS_PAD*4)
#define DEC_SMEM (((4*4*WSS + 4*WSS64) * 16) + 64*HS_PAD*4)

__global__ void __launch_bounds__(NTHR, 1) enc_kernel(
    const float* __restrict__ in_seq,
    const float4* __restrict__ pW0x, const float4* __restrict__ pW0h,
    const float4* __restrict__ pW1x, const float4* __restrict__ pW1h,
    const float4* __restrict__ pb0, const float4* __restrict__ pb1,
    const float* __restrict__ zerobuf,
    float* __restrict__ y0, float* __restrict__ h1A, float* __restrict__ h1B,
    float* __restrict__ c0out, float* __restrict__ c1out)
{
    extern __shared__ __align__(16) unsigned char smraw[];
    ulonglong2* W0h = (ulonglong2*)smraw;
    ulonglong2* W1x = W0h + 4 * WSS;
    ulonglong2* W1h = W1x + 4 * WSS;
    ulonglong2* W0x = W1h + 4 * WSS;
    float* hs = (float*)(W0x + 4 * WSS64);

    int tid = threadIdx.x, jl = tid & 3, r = tid >> 2;
    int j0 = blockIdx.x * 4, j = j0 + jl;
    int idx = (r << 9) + j;

    {   // load smem-resident weight tiles (once)
        const ulonglong2* g0h = (const ulonglong2*)pW0h + (size_t)j0 * HH;
        const ulonglong2* g1x = (const ulonglong2*)pW1x + (size_t)j0 * HH;
        const ulonglong2* g1h = (const ulonglong2*)pW1h + (size_t)j0 * HH;
#pragma unroll 2
        for (int i = tid; i < 4 * HH; i += NTHR) {
            int jj = i >> 9, kk = i & 511;
            W0h[jj * WSS + kk] = g0h[i];
            W1x[jj * WSS + kk] = g1x[i];
            W1h[jj * WSS + kk] = g1h[i];
        }
        const ulonglong2* g0x = (const ulonglong2*)pW0x + (size_t)j0 * FF;
        if (tid < 4 * FF) {
            int jj = tid >> 6, kk = tid & 63;
            W0x[jj * WSS64 + kk] = g0x[tid];
        }
    }
    float4 b0 = pb0[j], b1 = pb1[j];
    float c0 = 0.f, c1 = 0.f;
    __syncthreads();

    unsigned gen = 0;
    for (int slot = 0; slot <= TT; slot++) {
        bool doL0 = (slot < TT);
        bool doL1 = (slot > 0);
        ulonglong2 acc0, acc1;
        const float* yprev = (slot == 0) ? zerobuf : (y0 + (size_t)(slot - 1) * BH);

        if (doL0) {
            acc0.x = pack2(b0.x, b0.y); acc0.y = pack2(b0.z, b0.w);
            phase64(acc0, in_seq + (size_t)slot * FF, (long)TT * FF, W0x, hs, tid, jl, r);
        }
        if (doL1) { acc1.x = pack2(b1.x, b1.y); acc1.y = pack2(b1.z, b1.w); }

        if (doL0 && doL1)
            phase512<true, true>(acc0, acc1, yprev, W0h, W1x, hs, tid, jl, r);
        else if (doL0)
            phase512<true, false>(acc0, acc1, yprev, W0h, W1x, hs, tid, jl, r);
        else
            phase512<false, true>(acc0, acc1, yprev, W0h, W1x, hs, tid, jl, r);

        if (doL1) {
            const float* h1p = (slot == 1) ? zerobuf : ((slot & 1) ? h1A : h1B);
            phase512<false, true>(acc0, acc1, h1p, W0h, W1h, hs, tid, jl, r);
            float* h1o = (slot & 1) ? h1B : h1A;    // slot s -> buf[s&1]
            h1o[idx] = cellfin(acc1, c1);
        }
        if (doL0) y0[(size_t)slot * BH + idx] = cellfin(acc0, c0);

        gen++;
        grid_barrier(gen);
    }
    c0out[idx] = c0;
    c1out[idx] = c1;
    // final h1 is at slot TT (even) -> h1A
}

// ---------------- persistent decoder ----------------
__global__ void __launch_bounds__(NTHR, 1) dec_kernel(
    const float* __restrict__ in_seq,
    const float4* __restrict__ pWd0x, const float4* __restrict__ pWd0c,
    const float4* __restrict__ pWdh0, const float4* __restrict__ pWdx1,
    const float4* __restrict__ pWdh1,
    const float4* __restrict__ pbD0, const float4* __restrict__ pbD0c,
    const float4* __restrict__ pbD1,
    const float* __restrict__ h0init, const float* __restrict__ h1init,
    const float* __restrict__ c0in, const float* __restrict__ c1in,
    float* __restrict__ h0A, float* __restrict__ h0B, float* __restrict__ h1hist)
{
    extern __shared__ __align__(16) unsigned char smraw[];
    ulonglong2* Wc  = (ulonglong2*)smraw;
    ulonglong2* Wh0 = Wc  + 4 * WSS;
    ulonglong2* Wx1 = Wh0 + 4 * WSS;
    ulonglong2* Wh1 = Wx1 + 4 * WSS;
    ulonglong2* W0x = Wh1 + 4 * WSS;
    float* hs = (float*)(W0x + 4 * WSS64);

    int tid = threadIdx.x, jl = tid & 3, r = tid >> 2;
    int j0 = blockIdx.x * 4, j = j0 + jl;
    int idx = (r << 9) + j;

    {
        const ulonglong2* gc  = (const ulonglong2*)pWd0c + (size_t)j0 * HH;
        const ulonglong2* gh0 = (const ulonglong2*)pWdh0 + (size_t)j0 * HH;
        const ulonglong2* gx1 = (const ulonglong2*)pWdx1 + (size_t)j0 * HH;
        const ulonglong2* gh1 = (const ulonglong2*)pWdh1 + (size_t)j0 * HH;
#pragma unroll 2
        for (int i = tid; i < 4 * HH; i += NTHR) {
            int jj = i >> 9, kk = i & 511;
            Wc[jj * WSS + kk]  = gc[i];
            Wh0[jj * WSS + kk] = gh0[i];
            Wx1[jj * WSS + kk] = gx1[i];
            Wh1[jj * WSS + kk] = gh1[i];
        }
        const ulonglong2* g0x = (const ulonglong2*)pWd0x + (size_t)j0 * FF;
        if (tid < 4 * FF) {
            int jj = tid >> 6, kk = tid & 63;
            W0x[jj * WSS64 + kk] = g0x[tid];
        }
    }
    float4 bd0 = pbD0[j], bd0c = pbD0c[j], bd1 = pbD1[j];
    float c0 = c0in[idx], c1 = c1in[idx];
    __syncthreads();

    unsigned gen = 0;
    const float* h0prev = h0init;
    const float* h1prev = h1init;
    ulonglong2 dummy;

    for (int t = 0; t < FUT; t++) {
        // ---- cell d0 ----
        ulonglong2 a0;
        if (t == 0) {
            a0.x = pack2(bd0.x, bd0.y); a0.y = pack2(bd0.z, bd0.w);
            phase64(a0, in_seq + (size_t)(TT - 1) * FF, (long)TT * FF, W0x, hs, tid, jl, r);
        } else {
            a0.x = pack2(bd0c.x, bd0c.y); a0.y = pack2(bd0c.z, bd0c.w);
            phase512<true, false>(a0, dummy, h1hist + (size_t)(t - 1) * BH, Wc, Wc, hs, tid, jl, r);
        }
        phase512<true, false>(a0, dummy, h0prev, Wh0, Wh0, hs, tid, jl, r);
        float* h0out = (t & 1) ? h0B : h0A;
        h0out[idx] = cellfin(a0, c0);
        gen++; grid_barrier(gen);

        // ---- cell d1 ----
        ulonglong2 a1;
        a1.x = pack2(bd1.x, bd1.y); a1.y = pack2(bd1.z, bd1.w);
        phase512<true, false>(a1, dummy, h0out, Wx1, Wx1, hs, tid, jl, r);
        phase512<true, false>(a1, dummy, h1prev, Wh1, Wh1, hs, tid, jl, r);
        h1hist[(size_t)t * BH + idx] = cellfin(a1, c1);
        gen++; grid_barrier(gen);

        h0prev = h0out;
        h1prev = h1hist + (size_t)t * BH;
    }
}

// ---------------- packing / misc kernels ----------------
__global__ void pack_w_kernel(const float* __restrict__ W, float4* __restrict__ P, int Kin) {
    int idx = blockIdx.x * 256 + threadIdx.x;
    if (idx >= HH * Kin) return;
    int j = idx / Kin, k = idx - j * Kin;
    P[idx] = make_float4(W[j * Kin + k], W[(j + 512) * Kin + k],
                         W[(j + 1024) * Kin + k], W[(j + 1536) * Kin + k]);
}
__global__ void pack_b_kernel(const float* __restrict__ bih, const float* __restrict__ bhh,
                              float4* __restrict__ pb) {
    int j = blockIdx.x * 256 + threadIdx.x;
    if (j >= HH) return;
    pb[j] = make_float4(bih[j] + bhh[j], bih[j + 512] + bhh[j + 512],
                        bih[j + 1024] + bhh[j + 1024], bih[j + 1536] + bhh[j + 1536]);
}
__global__ void combine_dec0_kernel(const float4* __restrict__ pWih0, const float* __restrict__ fcW,
                                    const float4* __restrict__ pb0, const float* __restrict__ fcb,
                                    float4* __restrict__ Pc, float4* __restrict__ pbc) {
    int idx = blockIdx.x * 256 + threadIdx.x;
    if (idx >= HH * HH) return;
    int j = idx >> 9, hh = idx & 511;
    float4 acc = make_float4(0.f, 0.f, 0.f, 0.f);
#pragma unroll 8
    for (int n = 0; n < FF; n++) {
        float4 w = pWih0[(j << 6) + n];
        float f = fcW[(n << 9) + hh];
        acc.x += w.x * f; acc.y += w.y * f; acc.z += w.z * f; acc.w += w.w * f;
    }
    Pc[idx] = acc;
    if (hh == 0) {
        float4 bb = pb0[j];
#pragma unroll 8
        for (int n = 0; n < FF; n++) {
            float4 w = pWih0[(j << 6) + n];
            float f = fcb[n];
            bb.x += w.x * f; bb.y += w.y * f; bb.z += w.z * f; bb.w += w.w * f;
        }
        pbc[j] = bb;
    }
}
__global__ void init_kernel(float* zerobuf) {
    int i = blockIdx.x * 256 + threadIdx.x;
    if (i < BH) zerobuf[i] = 0.f;
    if (i == 0) { g_bcount = 0; g_bgen = 0; }
}
__global__ void reset_bar_kernel() {
    g_bcount = 0; g_bgen = 0;
}
// out[b][t][n] = fc_b[n] + sum_h h1hist[t][b][h] * fcW[n][h]
__global__ void final_fc_kernel(const float* __restrict__ h1hist, const float* __restrict__ fcW,
                                const float* __restrict__ fcb, float* __restrict__ out) {
    int t = blockIdx.y;
    int l = blockIdx.x * 256 + threadIdx.x;
    int b = l >> 6, n = l & 63;
    const float4* h4 = (const float4*)(h1hist + ((size_t)t * BB + b) * HH);
    const float4* w4 = (const float4*)(fcW + (size_t)n * HH);
    float acc = fcb[n];
#pragma unroll 8
    for (int k = 0; k < HH / 4; k++) {
        float4 a = h4[k], w = w4[k];
        acc += a.x * w.x + a.y * w.y + a.z * w.z + a.w * w.w;
    }
    out[((size_t)b * FUT + t) * FF + n] = acc;
}

// ---------------- host ----------------
extern "C" void kernel_launch(void* const* d_in, const int* in_sizes, int n_in,
                              void* d_out, int out_size) {
    const float* in_seq = (const float*)d_in[0];
    const float* eWih0  = (const float*)d_in[1];
    const float* eWhh0  = (const float*)d_in[2];
    const float* ebih0  = (const float*)d_in[3];
    const float* ebhh0  = (const float*)d_in[4];
    const float* eWih1  = (const float*)d_in[5];
    const float* eWhh1  = (const float*)d_in[6];
    const float* ebih1  = (const float*)d_in[7];
    const float* ebhh1  = (const float*)d_in[8];
    const float* dWih0  = (const float*)d_in[9];
    const float* dWhh0  = (const float*)d_in[10];
    const float* dbih0  = (const float*)d_in[11];
    const float* dbhh0  = (const float*)d_in[12];
    const float* dWih1  = (const float*)d_in[13];
    const float* dWhh1  = (const float*)d_in[14];
    const float* dbih1  = (const float*)d_in[15];
    const float* dbhh1  = (const float*)d_in[16];
    const float* fcW    = (const float*)d_in[17];
    const float* fcb    = (const float*)d_in[18];
    float* out = (float*)d_out;

    static int s_attr_done = 0;
    if (!s_attr_done) {
        cudaFuncSetAttribute(enc_kernel, cudaFuncAttributeMaxDynamicSharedMemorySize, ENC_SMEM);
        cudaFuncSetAttribute(dec_kernel, cudaFuncAttributeMaxDynamicSharedMemorySize, DEC_SMEM);
        s_attr_done = 1;
    }

    float4 *pWeih0, *pWehh0, *pWeih1, *pWehh1, *pWdih0, *pWdhh0, *pWdih1, *pWdhh1, *pWd0c;
    float4 *pbE0, *pbE1, *pbD0, *pbD1, *pbD0c;
    float *y0, *h1hist, *zerobuf, *c0, *c1, *h1A, *h1B, *h0A, *h0B;
    cudaGetSymbolAddress((void**)&y0,      g_y0);
    cudaGetSymbolAddress((void**)&h1hist,  g_h1hist);
    cudaGetSymbolAddress((void**)&zerobuf, g_zero);
    cudaGetSymbolAddress((void**)&c0,      g_c0);
    cudaGetSymbolAddress((void**)&c1,      g_c1);
    cudaGetSymbolAddress((void**)&h1A,     g_h1A);
    cudaGetSymbolAddress((void**)&h1B,     g_h1B);
    cudaGetSymbolAddress((void**)&h0A,     g_h0A);
    cudaGetSymbolAddress((void**)&h0B,     g_h0B);
    cudaGetSymbolAddress((void**)&pWeih0,  g_pW_enc_ih0);
    cudaGetSymbolAddress((void**)&pWehh0,  g_pW_enc_hh0);
    cudaGetSymbolAddress((void**)&pWeih1,  g_pW_enc_ih1);
    cudaGetSymbolAddress((void**)&pWehh1,  g_pW_enc_hh1);
    cudaGetSymbolAddress((void**)&pWdih0,  g_pW_dec_ih0);
    cudaGetSymbolAddress((void**)&pWdhh0,  g_pW_dec_hh0);
    cudaGetSymbolAddress((void**)&pWdih1,  g_pW_dec_ih1);
    cudaGetSymbolAddress((void**)&pWdhh1,  g_pW_dec_hh1);
    cudaGetSymbolAddress((void**)&pWd0c,   g_pW_dec0c);
    cudaGetSymbolAddress((void**)&pbE0,    g_pb_enc0);
    cudaGetSymbolAddress((void**)&pbE1,    g_pb_enc1);
    cudaGetSymbolAddress((void**)&pbD0,    g_pb_dec0);
    cudaGetSymbolAddress((void**)&pbD1,    g_pb_dec1);
    cudaGetSymbolAddress((void**)&pbD0c,   g_pb_dec0c);

    // --- pack weights/biases + init ---
    pack_w_kernel<<<(HH * FF + 255) / 256, 256>>>(eWih0, pWeih0, FF);
    pack_w_kernel<<<(HH * HH + 255) / 256, 256>>>(eWhh0, pWehh0, HH);
    pack_w_kernel<<<(HH * HH + 255) / 256, 256>>>(eWih1, pWeih1, HH);
    pack_w_kernel<<<(HH * HH + 255) / 256, 256>>>(eWhh1, pWehh1, HH);
    pack_w_kernel<<<(HH * FF + 255) / 256, 256>>>(dWih0, pWdih0, FF);
    pack_w_kernel<<<(HH * HH + 255) / 256, 256>>>(dWhh0, pWdhh0, HH);
    pack_w_kernel<<<(HH * HH + 255) / 256, 256>>>(dWih1, pWdih1, HH);
    pack_w_kernel<<<(HH * HH + 255) / 256, 256>>>(dWhh1, pWdhh1, HH);
    pack_b_kernel<<<2, 256>>>(ebih0, ebhh0, pbE0);
    pack_b_kernel<<<2, 256>>>(ebih1, ebhh1, pbE1);
    pack_b_kernel<<<2, 256>>>(dbih0, dbhh0, pbD0);
    pack_b_kernel<<<2, 256>>>(dbih1, dbhh1, pbD1);
    combine_dec0_kernel<<<(HH * HH + 255) / 256, 256>>>(pWdih0, fcW, pbD0, fcb, pWd0c, pbD0c);
    init_kernel<<<(BH + 255) / 256, 256>>>(zerobuf);

    // --- persistent encoder (513 slots, pipelined L0+L1) ---
    enc_kernel<<<NBLK, NTHR, ENC_SMEM>>>(
        in_seq, pWeih0, pWehh0, pWeih1, pWehh1, pbE0, pbE1,
        zerobuf, y0, h1A, h1B, c0, c1);

    reset_bar_kernel<<<1, 1>>>();

    // --- persistent decoder (96 steps x 2 cells) ---
    dec_kernel<<<NBLK, NTHR, DEC_SMEM>>>(
        in_seq, pWdih0, pWd0c, pWdhh0, pWdih1, pWdhh1,
        pbD0, pbD0c, pbD1,
        y0 + (size_t)(TT - 1) * BH, /* enc L0 final h */
        h1A,                        /* enc L1 final h (slot TT even) */
        c0, c1, h0A, h0B, h1hist);

    // --- batched final FC ---
    {
        dim3 grid(16, FUT);
        final_fc_kernel<<<grid, 256>>>(h1hist, fcW, fcb, out);
    }
}